// round 8
// baseline (speedup 1.0000x reference)
#include <cuda_runtime.h>
#include <math.h>
#include <limits.h>

// RewardModel fused kernel (one launch). Only rewards[b, last[b]] are consumed,
// so the [B,S,H]@[H] matvecs are never materialized. One block per batch row.
//
// Index algebra (vs reference):
//  - has_div is redundant: no divergence => arrays equal => r_ind_div == c_ind,
//    which equals the no-div branch min(c_ind, S). So last = min(c_ind,r_ind)-1
//    with both computed as "first PAD >= start".
//  - unfiltered collapse: pm = min over BOTH arrays of first PAD position.
//    If pm >= start, the start-filter is a no-op and last = pm - 1 directly
//    (one redux round). Only pm < start needs the filtered recompute (rare;
//    ids are already in registers).
//
// Inputs (metadata order):
//   0: chosen_ids int32 [B,S]   1: chosen_mask int32 [B,S]
//   2: rejected_ids int32 [B,S] 3: chosen_hidden fp32 [B,S,H]
//   4: rejected_hidden fp32 [B,S,H]  5: v_head_w fp32 [H]
// Output: fp32 [1 + 2B] = [loss, chosen_scores(B), rejected_scores(B)]

#define NT   512
#define MAXK 4              // fast path covers S <= NT*4*MAXK = 8192
#define NW   (NT >> 5)      // 16 warps

#define CNT_SHIFT 52        // arrival count in bits [52:64), sum in [0:52)
#define FIX_SCALE 4294967296.0   // 2^32 fixed point (softplus >= 0)

// zero-initialized; the finishing block resets it for the next graph replay
__device__ unsigned long long g_pack;

__global__ __launch_bounds__(NT)
void reward_fused_kernel(const int* __restrict__ chosen_ids,
                         const int* __restrict__ chosen_mask,
                         const int* __restrict__ rejected_ids,
                         const float* __restrict__ chosen_hidden,
                         const float* __restrict__ rejected_hidden,
                         const float* __restrict__ v_head_w,
                         float* __restrict__ out,
                         int B, int S, int H) {
    const int b    = blockIdx.x;
    const int tid  = threadIdx.x;
    const int warp = tid >> 5, lane = tid & 31;

    const int* cid = chosen_ids   + (size_t)b * S;
    const int* msk = chosen_mask  + (size_t)b * S;
    const int* rid = rejected_ids + (size_t)b * S;

    __shared__ int2   sh_i[NW];
    __shared__ float2 sh_s[NW];

    const int  K     = S / (NT * 4);
    const bool fastS = ((S & (NT * 4 - 1)) == 0) && (K >= 1) && (K <= MAXK);
    const bool fastH = (H == 1024);

    // ---- preload weights early (independent of the id scan; hides the load) ----
    float4 w4 = make_float4(0.f, 0.f, 0.f, 0.f);
    if (fastH && tid < 256) w4 = *(const float4*)(v_head_w + tid * 4);

    int last;

    if (fastS) {
        // ---- one front-batched load burst of all three id arrays ----
        int4 mv[MAXK], cv[MAXK], rv[MAXK];
        #pragma unroll
        for (int k = 0; k < MAXK; k++) {
            if (k < K) {
                const int off = k * NT * 4 + tid * 4;
                mv[k] = *(const int4*)(msk + off);
                cv[k] = *(const int4*)(cid + off);
                rv[k] = *(const int4*)(rid + off);
            }
        }
        // ls = first nonzero mask; pm = first PAD (==0) in EITHER sequence
        // (descending assignment -> min index wins)
        int ls = S, pm = S;
        #pragma unroll
        for (int k = MAXK - 1; k >= 0; k--) {
            if (k < K) {
                const int off = k * NT * 4 + tid * 4;
                if (mv[k].w)                    ls = off + 3;
                if (mv[k].z)                    ls = off + 2;
                if (mv[k].y)                    ls = off + 1;
                if (mv[k].x)                    ls = off;
                if (cv[k].w == 0 || rv[k].w == 0) pm = off + 3;
                if (cv[k].z == 0 || rv[k].z == 0) pm = off + 2;
                if (cv[k].y == 0 || rv[k].y == 0) pm = off + 1;
                if (cv[k].x == 0 || rv[k].x == 0) pm = off;
            }
        }
        // ---- ONE reduction round: (ls, pm); all threads combine redundantly ----
        ls = __reduce_min_sync(0xffffffffu, ls);
        pm = __reduce_min_sync(0xffffffffu, pm);
        if (lane == 0) sh_i[warp] = make_int2(ls, pm);
        __syncthreads();
        const int2 t = sh_i[lane & (NW - 1)];   // lanes 16-31 duplicate: min-safe
        const int s0 = __reduce_min_sync(0xffffffffu, t.x);
        const int p0 = __reduce_min_sync(0xffffffffu, t.y);
        const int start = (s0 == S) ? 0 : s0;   // argmax of all-false -> 0

        if (p0 >= start) {
            // start-filter is a no-op: last = p0 - 1 (p0==S -> S-1; p0==0 wraps)
            last = p0 - 1;
            if (last < 0) last += S;
        } else {
            // rare: some PAD precedes start; filtered recompute from registers
            int lc = S, lr = S;
            #pragma unroll
            for (int k = MAXK - 1; k >= 0; k--) {
                if (k < K) {
                    const int off = k * NT * 4 + tid * 4;
                    if (cv[k].w == 0 && off + 3 >= start) lc = off + 3;
                    if (cv[k].z == 0 && off + 2 >= start) lc = off + 2;
                    if (cv[k].y == 0 && off + 1 >= start) lc = off + 1;
                    if (cv[k].x == 0 && off     >= start) lc = off;
                    if (rv[k].w == 0 && off + 3 >= start) lr = off + 3;
                    if (rv[k].z == 0 && off + 2 >= start) lr = off + 2;
                    if (rv[k].y == 0 && off + 1 >= start) lr = off + 1;
                    if (rv[k].x == 0 && off     >= start) lr = off;
                }
            }
            lc = __reduce_min_sync(0xffffffffu, lc);
            lr = __reduce_min_sync(0xffffffffu, lr);
            if (lane == 0) sh_i[warp] = make_int2(lc, lr);
            __syncthreads();
            const int2 u = sh_i[lane & (NW - 1)];
            const int c0 = __reduce_min_sync(0xffffffffu, u.x);
            const int r0 = __reduce_min_sync(0xffffffffu, u.y);
            last = min(c0, r0) - 1;
            if (last < 0) last += S;            // JAX negative-index wrap
        }
    } else {
        // ---- generic fallback (two rounds) ----
        int ls = S;
        for (int s = tid; s < S; s += NT)
            if (msk[s]) { ls = s; break; }      // ascending stride -> first hit is min
        ls = __reduce_min_sync(0xffffffffu, ls);
        if (lane == 0) sh_i[warp] = make_int2(ls, 0);
        __syncthreads();
        const int s0 = __reduce_min_sync(0xffffffffu, sh_i[lane & (NW - 1)].x);
        const int start = (s0 == S) ? 0 : s0;

        int lc = S, lr = S;
        for (int s = tid; s < S; s += NT) {
            const int c = cid[s], r = rid[s];
            if (s >= start) {
                if (c == 0 && s < lc) lc = s;
                if (r == 0 && s < lr) lr = s;
            }
        }
        lc = __reduce_min_sync(0xffffffffu, lc);
        lr = __reduce_min_sync(0xffffffffu, lr);
        __syncthreads();
        if (lane == 0) sh_i[warp] = make_int2(lc, lr);
        __syncthreads();
        const int2 u = sh_i[lane & (NW - 1)];
        const int c0 = __reduce_min_sync(0xffffffffu, u.x);
        const int r0 = __reduce_min_sync(0xffffffffu, u.y);
        last = min(c0, r0) - 1;
        if (last < 0) last += S;
    }

    // ---- dot products at the score position ----
    const float* ch = chosen_hidden   + ((size_t)b * S + last) * H;
    const float* rh = rejected_hidden + ((size_t)b * S + last) * H;

    float ac = 0.f, ar = 0.f;
    if (fastH) {
        if (tid < 256) {                        // one float4 of each row per thread
            const float4 c4 = *(const float4*)(ch + tid * 4);
            const float4 r4 = *(const float4*)(rh + tid * 4);
            ac = c4.x * w4.x + c4.y * w4.y + c4.z * w4.z + c4.w * w4.w;
            ar = r4.x * w4.x + r4.y * w4.y + r4.z * w4.z + r4.w * w4.w;
        }
    } else {
        for (int h = tid; h < H; h += NT) {
            const float w = v_head_w[h];
            ac += ch[h] * w;
            ar += rh[h] * w;
        }
    }

    #pragma unroll
    for (int o = 16; o; o >>= 1) {
        ac += __shfl_down_sync(0xffffffffu, ac, o);
        ar += __shfl_down_sync(0xffffffffu, ar, o);
    }
    if (lane == 0) sh_s[warp] = make_float2(ac, ar);
    __syncthreads();

    if (warp == 0) {
        float cs, rs;
        if (fastH) {
            // partials live in warps 0-7: chosen in lanes 0-7, rejected in 8-15
            float v = (lane < 8) ? sh_s[lane].x
                    : ((lane < 16) ? sh_s[lane - 8].y : 0.f);
            #pragma unroll
            for (int o = 4; o; o >>= 1) v += __shfl_xor_sync(0xffffffffu, v, o);
            cs = __shfl_sync(0xffffffffu, v, 0);
            rs = __shfl_sync(0xffffffffu, v, 8);
        } else {
            float xc = (lane < NW) ? sh_s[lane].x : 0.f;
            float xr = (lane < NW) ? sh_s[lane].y : 0.f;
            #pragma unroll
            for (int o = 8; o; o >>= 1) {
                xc += __shfl_xor_sync(0xffffffffu, xc, o);
                xr += __shfl_xor_sync(0xffffffffu, xr, o);
            }
            cs = xc; rs = xr;
        }
        if (lane == 0) {
            out[1 + b]     = cs;
            out[1 + B + b] = rs;

            // -log_sigmoid(cs - rs) = softplus(rs - cs), numerically stable, >= 0
            const float d  = cs - rs;
            const float lv = fmaxf(-d, 0.f) + log1pf(expf(-fabsf(d)));

            // ONE packed atomic: arrival count high bits, fixed-point sum low.
            // Integer adds commute -> exact determinism across replays.
            const unsigned long long mine =
                (1ULL << CNT_SHIFT) |
                (unsigned long long)__double2ll_rn((double)lv * FIX_SCALE);
            const unsigned long long old = atomicAdd(&g_pack, mine);
            if ((old >> CNT_SHIFT) == (unsigned long long)(gridDim.x - 1)) {
                const unsigned long long total =
                    (old + mine) & ((1ULL << CNT_SHIFT) - 1ULL);
                out[0] = (float)((double)total * (1.0 / FIX_SCALE) / (double)B);
                atomicExch(&g_pack, 0ULL);   // reset for the next graph replay
            }
        }
    }
}

extern "C" void kernel_launch(void* const* d_in, const int* in_sizes, int n_in,
                              void* d_out, int out_size) {
    const int*   chosen_ids      = (const int*)  d_in[0];
    const int*   chosen_mask     = (const int*)  d_in[1];
    const int*   rejected_ids    = (const int*)  d_in[2];
    const float* chosen_hidden   = (const float*)d_in[3];
    const float* rejected_hidden = (const float*)d_in[4];
    const float* v_head_w        = (const float*)d_in[5];
    float*       out             = (float*)d_out;

    const int B = (out_size - 1) / 2;   // out = [loss, chosen(B), rejected(B)]
    const int S = in_sizes[0] / B;      // chosen_ids is [B,S]
    const int H = in_sizes[5];          // v_head_w is [H]

    reward_fused_kernel<<<B, NT>>>(chosen_ids, chosen_mask, rejected_ids,
                                   chosen_hidden, rejected_hidden, v_head_w,
                                   out, B, S, H);
}

// round 9
// speedup vs baseline: 1.0295x; 1.0295x over previous
#include <cuda_runtime.h>
#include <math.h>
#include <limits.h>

// RewardModel fused kernel (one launch). Only rewards[b, last[b]] are consumed,
// so the [B,S,H]@[H] matvecs are never materialized. One block per batch row.
//
// Index algebra (vs reference):
//  - has_div is redundant: no divergence => arrays equal => r_ind_div == c_ind.
//  - pm = unfiltered min over BOTH arrays of first PAD position. If pm >= start
//    the start-filter is a no-op and last = pm - 1 directly (one redux round).
//    Only pm < start needs the filtered recompute (rare; ids are in registers).
//
// Critical-path design: common path has ONE __syncthreads. After it, warps
// 1..15 exit; warp 0 alone gathers weights + both hidden rows (24 independent
// LDG.128 per lane) and reduces with two fixed-point __reduce_add_sync —
// no shuffle chains, no shared-memory combine, no second barrier.
//
// Inputs (metadata order):
//   0: chosen_ids int32 [B,S]   1: chosen_mask int32 [B,S]
//   2: rejected_ids int32 [B,S] 3: chosen_hidden fp32 [B,S,H]
//   4: rejected_hidden fp32 [B,S,H]  5: v_head_w fp32 [H]
// Output: fp32 [1 + 2B] = [loss, chosen_scores(B), rejected_scores(B)]

#define NT   512
#define MAXK 4                   // fast path covers S <= NT*4*MAXK = 8192
#define NW   (NT >> 5)           // 16 warps

#define CNT_SHIFT 52             // arrival count in bits [52:64), sum in [0:52)
#define FIX_SCALE 4294967296.0   // 2^32 fixed point for the loss sum
#define DOT_SCALE 16777216.0f    // 2^24 fixed point for score partials

// zero-initialized; the finishing block resets it for the next graph replay
__device__ unsigned long long g_pack;

__global__ __launch_bounds__(NT)
void reward_fused_kernel(const int* __restrict__ chosen_ids,
                         const int* __restrict__ chosen_mask,
                         const int* __restrict__ rejected_ids,
                         const float* __restrict__ chosen_hidden,
                         const float* __restrict__ rejected_hidden,
                         const float* __restrict__ v_head_w,
                         float* __restrict__ out,
                         int B, int S, int H) {
    const int b    = blockIdx.x;
    const int tid  = threadIdx.x;
    const int warp = tid >> 5, lane = tid & 31;

    const int* cid = chosen_ids   + (size_t)b * S;
    const int* msk = chosen_mask  + (size_t)b * S;
    const int* rid = rejected_ids + (size_t)b * S;

    __shared__ int2   sh_i[NW];
    __shared__ float2 sh_s[NW];

    const int  K     = S / (NT * 4);
    const bool fastS = ((S & (NT * 4 - 1)) == 0) && (K >= 1) && (K <= MAXK);
    const bool fastH = (H == 1024);

    int last;

    if (fastS) {
        // ---- one front-batched load burst of all three id arrays ----
        int4 mv[MAXK], cv[MAXK], rv[MAXK];
        #pragma unroll
        for (int k = 0; k < MAXK; k++) {
            if (k < K) {
                const int off = k * NT * 4 + tid * 4;
                mv[k] = *(const int4*)(msk + off);
                cv[k] = *(const int4*)(cid + off);
                rv[k] = *(const int4*)(rid + off);
            }
        }
        // ls = first nonzero mask; pm = first PAD (==0) in EITHER sequence.
        // Predicated candidates + min trees (parallel SEL + IMNMX, no serial chain).
        int ls = S, pm = S;
        #pragma unroll
        for (int k = 0; k < MAXK; k++) {
            if (k < K) {
                const int off = k * NT * 4 + tid * 4;
                const int m0 = mv[k].x ? off     : S;
                const int m1 = mv[k].y ? off + 1 : S;
                const int m2 = mv[k].z ? off + 2 : S;
                const int m3 = mv[k].w ? off + 3 : S;
                ls = min(ls, min(min(m0, m1), min(m2, m3)));
                const int p0_ = (cv[k].x == 0 || rv[k].x == 0) ? off     : S;
                const int p1_ = (cv[k].y == 0 || rv[k].y == 0) ? off + 1 : S;
                const int p2_ = (cv[k].z == 0 || rv[k].z == 0) ? off + 2 : S;
                const int p3_ = (cv[k].w == 0 || rv[k].w == 0) ? off + 3 : S;
                pm = min(pm, min(min(p0_, p1_), min(p2_, p3_)));
            }
        }
        // ---- ONE reduction round, ONE barrier ----
        ls = __reduce_min_sync(0xffffffffu, ls);
        pm = __reduce_min_sync(0xffffffffu, pm);
        if (lane == 0) sh_i[warp] = make_int2(ls, pm);
        __syncthreads();
        const int2 t = sh_i[lane & (NW - 1)];   // lanes 16-31 duplicate: min-safe
        const int s0 = __reduce_min_sync(0xffffffffu, t.x);
        const int p0 = __reduce_min_sync(0xffffffffu, t.y);
        const int start = (s0 == S) ? 0 : s0;   // argmax of all-false -> 0

        if (p0 >= start) {
            // no PAD precedes start: filter is a no-op, last = p0 - 1 (wrap if -1)
            last = p0 - 1;
            if (last < 0) last += S;
        } else {
            // rare: filtered recompute from registers (all warps, one more round)
            int lc = S, lr = S;
            #pragma unroll
            for (int k = MAXK - 1; k >= 0; k--) {
                if (k < K) {
                    const int off = k * NT * 4 + tid * 4;
                    if (cv[k].w == 0 && off + 3 >= start) lc = off + 3;
                    if (cv[k].z == 0 && off + 2 >= start) lc = off + 2;
                    if (cv[k].y == 0 && off + 1 >= start) lc = off + 1;
                    if (cv[k].x == 0 && off     >= start) lc = off;
                    if (rv[k].w == 0 && off + 3 >= start) lr = off + 3;
                    if (rv[k].z == 0 && off + 2 >= start) lr = off + 2;
                    if (rv[k].y == 0 && off + 1 >= start) lr = off + 1;
                    if (rv[k].x == 0 && off     >= start) lr = off;
                }
            }
            lc = __reduce_min_sync(0xffffffffu, lc);
            lr = __reduce_min_sync(0xffffffffu, lr);
            if (lane == 0) sh_i[warp] = make_int2(lc, lr);
            __syncthreads();
            const int2 u = sh_i[lane & (NW - 1)];
            const int c0 = __reduce_min_sync(0xffffffffu, u.x);
            const int r0 = __reduce_min_sync(0xffffffffu, u.y);
            last = min(c0, r0) - 1;
            if (last < 0) last += S;            // JAX negative-index wrap
        }
    } else {
        // ---- generic fallback ----
        int ls = S;
        for (int s = tid; s < S; s += NT)
            if (msk[s]) { ls = s; break; }      // ascending stride -> first hit is min
        ls = __reduce_min_sync(0xffffffffu, ls);
        if (lane == 0) sh_i[warp] = make_int2(ls, 0);
        __syncthreads();
        const int s0 = __reduce_min_sync(0xffffffffu, sh_i[lane & (NW - 1)].x);
        const int start = (s0 == S) ? 0 : s0;

        int lc = S, lr = S;
        for (int s = tid; s < S; s += NT) {
            const int c = cid[s], r = rid[s];
            if (s >= start) {
                if (c == 0 && s < lc) lc = s;
                if (r == 0 && s < lr) lr = s;
            }
        }
        lc = __reduce_min_sync(0xffffffffu, lc);
        lr = __reduce_min_sync(0xffffffffu, lr);
        __syncthreads();
        if (lane == 0) sh_i[warp] = make_int2(lc, lr);
        __syncthreads();
        const int2 u = sh_i[lane & (NW - 1)];
        const int c0 = __reduce_min_sync(0xffffffffu, u.x);
        const int r0 = __reduce_min_sync(0xffffffffu, u.y);
        last = min(c0, r0) - 1;
        if (last < 0) last += S;
    }

    if (fastH) {
        // ---- single-warp dual dot: no barriers, no shared combine ----
        if (warp != 0) return;                  // 15 warps done; warp 0 finishes

        const float* ch = chosen_hidden   + ((size_t)b * S + last) * H;
        const float* rh = rejected_hidden + ((size_t)b * S + last) * H;

        float ac = 0.f, ar = 0.f;
        #pragma unroll
        for (int j = 0; j < 8; j++) {           // 24 independent LDG.128 per lane
            const int e = lane * 4 + j * 128;
            const float4 w  = *(const float4*)(v_head_w + e);
            const float4 c4 = *(const float4*)(ch + e);
            const float4 r4 = *(const float4*)(rh + e);
            ac += c4.x * w.x + c4.y * w.y + c4.z * w.z + c4.w * w.w;
            ar += r4.x * w.x + r4.y * w.y + r4.z * w.z + r4.w * w.w;
        }

        // fixed-point warp reduction: one REDUX per value instead of a 5-deep
        // shuffle chain; integer adds are order-independent (deterministic).
        int ia = __float2int_rn(ac * DOT_SCALE);
        int ib = __float2int_rn(ar * DOT_SCALE);
        ia = __reduce_add_sync(0xffffffffu, ia);
        ib = __reduce_add_sync(0xffffffffu, ib);

        if (lane == 0) {
            const float cs = (float)ia * (1.0f / DOT_SCALE);
            const float rs = (float)ib * (1.0f / DOT_SCALE);
            out[1 + b]     = cs;
            out[1 + B + b] = rs;

            // -log_sigmoid(cs - rs) = softplus(rs - cs), numerically stable, >= 0
            const float d  = cs - rs;
            const float lv = fmaxf(-d, 0.f) + log1pf(expf(-fabsf(d)));

            // ONE packed atomic: arrival count high bits, fixed-point sum low.
            const unsigned long long mine =
                (1ULL << CNT_SHIFT) |
                (unsigned long long)__double2ll_rn((double)lv * FIX_SCALE);
            const unsigned long long old = atomicAdd(&g_pack, mine);
            if ((old >> CNT_SHIFT) == (unsigned long long)(gridDim.x - 1)) {
                const unsigned long long total =
                    (old + mine) & ((1ULL << CNT_SHIFT) - 1ULL);
                out[0] = (float)((double)total * (1.0 / FIX_SCALE) / (double)B);
                atomicExch(&g_pack, 0ULL);      // reset for the next graph replay
            }
        }
        return;
    }

    // ---- generic-H path: all threads strided dot + shared combine ----
    {
        const float* ch = chosen_hidden   + ((size_t)b * S + last) * H;
        const float* rh = rejected_hidden + ((size_t)b * S + last) * H;
        float ac = 0.f, ar = 0.f;
        for (int h = tid; h < H; h += NT) {
            const float w = v_head_w[h];
            ac += ch[h] * w;
            ar += rh[h] * w;
        }
        #pragma unroll
        for (int o = 16; o; o >>= 1) {
            ac += __shfl_down_sync(0xffffffffu, ac, o);
            ar += __shfl_down_sync(0xffffffffu, ar, o);
        }
        if (lane == 0) sh_s[warp] = make_float2(ac, ar);
        __syncthreads();
        if (warp == 0) {
            float xc = (lane < NW) ? sh_s[lane].x : 0.f;
            float xr = (lane < NW) ? sh_s[lane].y : 0.f;
            #pragma unroll
            for (int o = 8; o; o >>= 1) {
                xc += __shfl_xor_sync(0xffffffffu, xc, o);
                xr += __shfl_xor_sync(0xffffffffu, xr, o);
            }
            if (lane == 0) {
                out[1 + b]     = xc;
                out[1 + B + b] = xr;
                const float d  = xc - xr;
                const float lv = fmaxf(-d, 0.f) + log1pf(expf(-fabsf(d)));
                const unsigned long long mine =
                    (1ULL << CNT_SHIFT) |
                    (unsigned long long)__double2ll_rn((double)lv * FIX_SCALE);
                const unsigned long long old = atomicAdd(&g_pack, mine);
                if ((old >> CNT_SHIFT) == (unsigned long long)(gridDim.x - 1)) {
                    const unsigned long long total =
                        (old + mine) & ((1ULL << CNT_SHIFT) - 1ULL);
                    out[0] = (float)((double)total * (1.0 / FIX_SCALE) / (double)B);
                    atomicExch(&g_pack, 0ULL);
                }
            }
        }
    }
}

extern "C" void kernel_launch(void* const* d_in, const int* in_sizes, int n_in,
                              void* d_out, int out_size) {
    const int*   chosen_ids      = (const int*)  d_in[0];
    const int*   chosen_mask     = (const int*)  d_in[1];
    const int*   rejected_ids    = (const int*)  d_in[2];
    const float* chosen_hidden   = (const float*)d_in[3];
    const float* rejected_hidden = (const float*)d_in[4];
    const float* v_head_w        = (const float*)d_in[5];
    float*       out             = (float*)d_out;

    const int B = (out_size - 1) / 2;   // out = [loss, chosen(B), rejected(B)]
    const int S = in_sizes[0] / B;      // chosen_ids is [B,S]
    const int H = in_sizes[5];          // v_head_w is [H]

    reward_fused_kernel<<<B, NT>>>(chosen_ids, chosen_mask, rejected_ids,
                                   chosen_hidden, rejected_hidden, v_head_w,
                                   out, B, S, H);
}